// round 1
// baseline (speedup 1.0000x reference)
#include <cuda_runtime.h>

#define DD 128
#define HW 128
#define TILE 32
#define HALO 36
#define PLANE (HALO * HALO)       // 1296
#define CZ 16
#define NCH 8                      // N*C = 2*4
#define NTHREADS 256
#define ZB_STRIDE 37
#define ZB_FIELD (HALO * ZB_STRIDE)   // 1332
#define YB_STRIDE 37
#define YB_FIELD (TILE * YB_STRIDE)   // 1184

__device__ float g_w[5];
__device__ double g_sum;

// Extract separable 1-D weights from the 3-D Gaussian (w[i] = plane-i sum),
// and zero the global accumulator. Runs every launch (deterministic).
__global__ void ssim_init(const float* __restrict__ kern) {
    if (threadIdx.x == 0) g_sum = 0.0;
    if (threadIdx.x < 5) {
        float s = 0.f;
        #pragma unroll
        for (int j = 0; j < 25; ++j) s += kern[threadIdx.x * 25 + j];
        g_w[threadIdx.x] = s;
    }
}

__global__ __launch_bounds__(NTHREADS)
void ssim_main(const float* __restrict__ xg_all, const float* __restrict__ yg_all) {
    extern __shared__ float smem[];
    float* ringx = smem;                       // [5][PLANE]
    float* ringy = ringx + 5 * PLANE;          // [5][PLANE]
    float* zbuf  = ringy + 5 * PLANE;          // [5][ZB_FIELD]
    float* ybuf  = zbuf + 5 * ZB_FIELD;        // [5][YB_FIELD]
    __shared__ float wred[8];

    const int tid = threadIdx.x;
    const int w0 = blockIdx.x * TILE;
    const int h0 = blockIdx.y * TILE;
    const int zc = blockIdx.z & 7;             // 8 z-chunks
    const int nc = blockIdx.z >> 3;            // 8 (n,c) slabs
    const int z0 = zc * CZ;

    const float* xg = xg_all + (size_t)nc * (DD * HW * HW);
    const float* yg = yg_all + (size_t)nc * (DD * HW * HW);

    float wk[5];
    #pragma unroll
    for (int i = 0; i < 5; ++i) wk[i] = g_w[i];

    auto load_plane = [&](int zp) {
        int slot = (zp + 10) % 5;
        float* rx = ringx + slot * PLANE;
        float* ry = ringy + slot * PLANE;
        if ((unsigned)zp >= (unsigned)DD) {
            for (int p = tid; p < PLANE; p += NTHREADS) { rx[p] = 0.f; ry[p] = 0.f; }
        } else {
            const float* xp = xg + (size_t)zp * (HW * HW);
            const float* yp = yg + (size_t)zp * (HW * HW);
            for (int p = tid; p < PLANE; p += NTHREADS) {
                int r = p / HALO;
                int c = p - r * HALO;
                int hg = h0 + r - 2;
                int wg = w0 + c - 2;
                float xv = 0.f, yv = 0.f;
                if ((unsigned)hg < (unsigned)HW && (unsigned)wg < (unsigned)HW) {
                    int o = hg * HW + wg;
                    xv = (xp[o] + 1.f) * 0.5f;   // (x+1)*0.5 fused at load
                    yv = (yp[o] + 1.f) * 0.5f;
                }
                rx[p] = xv;
                ry[p] = yv;
            }
        }
    };

    // Prime ring with planes z0-2 .. z0+1 (first loop iteration loads z0+2).
    for (int zp = z0 - 2; zp <= z0 + 1; ++zp) load_plane(zp);

    float lsum = 0.f;
    for (int z = z0; z < z0 + CZ; ++z) {
        load_plane(z + 2);
        __syncthreads();

        // ---- z-pass: conv along depth, producing 5 fields over the 36x36 halo ----
        int s0 = (z + 8) % 5;   // slot of plane z-2
        for (int p = tid; p < PLANE; p += NTHREADS) {
            float ax = 0.f, ay = 0.f, axx = 0.f, ayy = 0.f, axy = 0.f;
            #pragma unroll
            for (int dz = 0; dz < 5; ++dz) {
                int s = s0 + dz; if (s >= 5) s -= 5;
                float xv = ringx[s * PLANE + p];
                float yv = ringy[s * PLANE + p];
                float wv = wk[dz];
                ax  += wv * xv;
                ay  += wv * yv;
                axx += wv * xv * xv;
                ayy += wv * yv * yv;
                axy += wv * xv * yv;
            }
            int r = p / HALO;
            int c = p - r * HALO;
            int zo = r * ZB_STRIDE + c;
            zbuf[0 * ZB_FIELD + zo] = ax;
            zbuf[1 * ZB_FIELD + zo] = ay;
            zbuf[2 * ZB_FIELD + zo] = axx;
            zbuf[3 * ZB_FIELD + zo] = ayy;
            zbuf[4 * ZB_FIELD + zo] = axy;
        }
        __syncthreads();

        // ---- y-pass: conv along H; 288 jobs, each produces 4 h-rows via sliding window ----
        for (int j = tid; j < HALO * (TILE / 4); j += NTHREADS) {
            int c  = j % HALO;
            int hb = (j / HALO) * 4;
            #pragma unroll
            for (int f = 0; f < 5; ++f) {
                float v[8];
                #pragma unroll
                for (int k = 0; k < 8; ++k)
                    v[k] = zbuf[f * ZB_FIELD + (hb + k) * ZB_STRIDE + c];
                #pragma unroll
                for (int i = 0; i < 4; ++i) {
                    float a = wk[0] * v[i]     + wk[1] * v[i + 1] + wk[2] * v[i + 2]
                            + wk[3] * v[i + 3] + wk[4] * v[i + 4];
                    ybuf[f * YB_FIELD + (hb + i) * YB_STRIDE + c] = a;
                }
            }
        }
        __syncthreads();

        // ---- x-pass + SSIM: exactly 256 jobs (one per thread), 4 outputs each ----
        {
            int h  = tid >> 3;
            int wb = (tid & 7) * 4;
            float acc[5][4];
            #pragma unroll
            for (int f = 0; f < 5; ++f) {
                float v[8];
                #pragma unroll
                for (int k = 0; k < 8; ++k)
                    v[k] = ybuf[f * YB_FIELD + h * YB_STRIDE + wb + k];
                #pragma unroll
                for (int i = 0; i < 4; ++i)
                    acc[f][i] = wk[0] * v[i]     + wk[1] * v[i + 1] + wk[2] * v[i + 2]
                              + wk[3] * v[i + 3] + wk[4] * v[i + 4];
            }
            const float c1 = 1e-4f;   // 0.01^2
            const float c2 = 9e-4f;   // 0.03^2
            #pragma unroll
            for (int i = 0; i < 4; ++i) {
                float mu1 = acc[0][i], mu2 = acc[1][i];
                float mu1s = mu1 * mu1, mu2s = mu2 * mu2, mu12 = mu1 * mu2;
                float s1  = acc[2][i] - mu1s;
                float s2  = acc[3][i] - mu2s;
                float s12 = acc[4][i] - mu12;
                float num = (2.f * mu12 + c1) * (2.f * s12 + c2);
                float den = (mu1s + mu2s + c1) * (s1 + s2 + c2);
                lsum += __fdividef(num, den);
            }
        }
        // next iteration's load_plane is gated by the syncs above; no extra barrier needed
    }

    // ---- block reduction -> one fp64 atomic per block ----
    #pragma unroll
    for (int o = 16; o > 0; o >>= 1)
        lsum += __shfl_down_sync(0xffffffffu, lsum, o);
    if ((tid & 31) == 0) wred[tid >> 5] = lsum;
    __syncthreads();
    if (tid < 32) {
        float v = (tid < 8) ? wred[tid] : 0.f;
        #pragma unroll
        for (int o = 4; o > 0; o >>= 1)
            v += __shfl_down_sync(0xffffffffu, v, o);
        if (tid == 0) atomicAdd(&g_sum, (double)v);
    }
}

__global__ void ssim_fin(float* __restrict__ out, int n) {
    float v = (float)(g_sum / (double)(2LL * 4 * 128 * 128 * 128));
    for (int i = threadIdx.x; i < n; i += blockDim.x) out[i] = v;
}

extern "C" void kernel_launch(void* const* d_in, const int* in_sizes, int n_in,
                              void* d_out, int out_size) {
    const float* x = (const float*)d_in[0];
    const float* y = (const float*)d_in[1];
    const float* k = (const float*)d_in[2];
    float* out = (float*)d_out;

    size_t smem = (size_t)(10 * PLANE + 5 * ZB_FIELD + 5 * YB_FIELD) * sizeof(float); // 102160 B
    cudaFuncSetAttribute(ssim_main, cudaFuncAttributeMaxDynamicSharedMemorySize, (int)smem);

    ssim_init<<<1, 32>>>(k);
    dim3 grid(HW / TILE, HW / TILE, (DD / CZ) * NCH);   // 4 x 4 x 64
    ssim_main<<<grid, NTHREADS, smem>>>(x, y);
    ssim_fin<<<1, 256>>>(out, out_size);
}